// round 9
// baseline (speedup 1.0000x reference)
#include <cuda_runtime.h>
#include <cuda_bf16.h>
#include <math.h>
#include <stdint.h>

#define SS 2048
#define BB 32
#define DD 256
#define HH 4
#define NROWS (SS*BB)          // 65536
#define EPS 1e-5f

// ---------------- scratch (static device globals; no allocations) ----------
__device__ float g_buf[(size_t)8 * NROWS * DD];        // fp32 Q,K,V,T1,T2 slabs
__device__ float g_psum[512][2][DD];                   // per-CTA stats partials
__device__ float g_pmid[32][2][DD];
__device__ float g_scale[DD];
__device__ float g_shift[DD];
__device__ float g_sm_m[16][BB][DD];
__device__ float g_sm_l[16][BB][DD];
__device__ float g_sm_a[16][BB][DD];
__device__ float g_headout[BB][HH*DD];
__device__ float g_mlp0[BB][DD];
__device__ float g_mlp1[BB][DD];
__device__ __nv_bfloat16 g_whi[20][DD*DD];             // weights hi
__device__ __nv_bfloat16 g_wlo[20][DD*DD];             // weights lo
// activation bf16 hi/lo, 6 slots: [0..2]=heads even write Q,K,V; [3..5]=odd/input
__device__ __nv_bfloat16 g_ahi[(size_t)6 * NROWS * DD];
__device__ __nv_bfloat16 g_alo[(size_t)6 * NROWS * DD];

// ======================= helpers ==========================================
__device__ __forceinline__ uint32_t smem_u32(const void* p) {
    uint32_t a;
    asm("{ .reg .u64 t; cvta.to.shared.u64 t, %1; cvt.u32.u64 %0, t; }"
        : "=r"(a) : "l"(p));
    return a;
}
__device__ __forceinline__ uint32_t swz(uint32_t off) {   // 64B-row swizzle
    return off ^ ((off >> 3) & 0x30);
}
__device__ __forceinline__ void ldsm4(uint32_t& r0, uint32_t& r1,
                                      uint32_t& r2, uint32_t& r3, uint32_t addr) {
    asm volatile("ldmatrix.sync.aligned.m8n8.x4.shared.b16 {%0,%1,%2,%3}, [%4];"
                 : "=r"(r0), "=r"(r1), "=r"(r2), "=r"(r3) : "r"(addr));
}
__device__ __forceinline__ void mma_bf16(float* d, const uint32_t* a,
                                         uint32_t b0, uint32_t b1) {
    asm volatile(
        "mma.sync.aligned.m16n8k16.row.col.f32.bf16.bf16.f32 "
        "{%0,%1,%2,%3},{%4,%5,%6,%7},{%8,%9},{%0,%1,%2,%3};"
        : "+f"(d[0]), "+f"(d[1]), "+f"(d[2]), "+f"(d[3])
        : "r"(a[0]), "r"(a[1]), "r"(a[2]), "r"(a[3]), "r"(b0), "r"(b1));
}
__device__ __forceinline__ void cpasync16(uint32_t dst, const void* src) {
    asm volatile("cp.async.ca.shared.global [%0], [%1], 16;" :: "r"(dst), "l"(src));
}
__device__ __forceinline__ unsigned short bf_hi(float x, float& rem) {
    __nv_bfloat16 h = __float2bfloat16_rn(x);
    rem = x - __bfloat162float(h);
    return __bfloat16_as_ushort(h);
}
__device__ __forceinline__ unsigned short bf_rn(float x) {
    return __bfloat16_as_ushort(__float2bfloat16_rn(x));
}

// ===========================================================================
// Weight pre-split
// ===========================================================================
__global__ void wconv_k(const float* __restrict__ wq, const float* __restrict__ wk,
                        const float* __restrict__ wv, const float* __restrict__ wl1,
                        const float* __restrict__ wl2)
{
    int idx = blockIdx.x * blockDim.x + threadIdx.x;
    int t = idx >> 18;
    int r = idx & 0x3FFFF;
    const float* src = (t == 0 ? wq : t == 1 ? wk : t == 2 ? wv : t == 3 ? wl1 : wl2);
    float x = src[r];
    int h = r >> 16;
    int e = r & 0xFFFF;
    int slot = h * 5 + t;
    float rem;
    unsigned short hi = bf_hi(x, rem);
    g_whi[slot][e] = __ushort_as_bfloat16(hi);
    g_wlo[slot][e] = __ushort_as_bfloat16(bf_rn(rem));
}

// ===========================================================================
// Input pre-split: q,k,v fp32 -> bf16 hi/lo into slots 3,4,5 (read by head 0)
// ===========================================================================
__global__ void insplit_k(const float* __restrict__ q, const float* __restrict__ k,
                          const float* __restrict__ v)
{
    const int t = blockIdx.y;
    const float* src = (t == 0) ? q : (t == 1) ? k : v;
    const size_t base = (size_t)(3 + t) * NROWS * DD;
    const size_t i = ((size_t)blockIdx.x * blockDim.x + threadIdx.x) * 4;
    float4 x = *(const float4*)(src + i);
    float r0, r1, r2, r3;
    unsigned int h01 = bf_hi(x.x, r0) | ((unsigned int)bf_hi(x.y, r1) << 16);
    unsigned int h23 = bf_hi(x.z, r2) | ((unsigned int)bf_hi(x.w, r3) << 16);
    unsigned int l01 = bf_rn(r0) | ((unsigned int)bf_rn(r1) << 16);
    unsigned int l23 = bf_rn(r2) | ((unsigned int)bf_rn(r3) << 16);
    *(uint2*)(g_ahi + base + i) = make_uint2(h01, h23);
    *(uint2*)(g_alo + base + i) = make_uint2(l01, l23);
}

// ===========================================================================
// HMMA GEMM: C = f(A) @ W^T + bias   (split bf16 x3)
//   MODE 0: identity;  MODE 1: relu((A1-A2)*scale+shift);  MODE 2: relu(A1*scale+shift)
//   STATS 0: none; 1: per-col sum/sumsq of output; 2: of (output - D2)
//   ABF16: A supplied pre-split bf16 hi/lo, loaded via cp.async (MODE must be 0)
//   WB:    epilogue additionally writes bf16 hi/lo copy of C (for next head)
// CTA 128x64, 8 warps (4M x 2N, 32x32 warp tiles), 2-stage cp.async pipeline.
// ===========================================================================
#define BM 128
#define BNT 64
#define BK 32
#define NCH (DD/BK)            // 8

#define ST_SZ   24576          // per stage: Ah 8K, Al 8K, Wh 4K, Wl 4K
#define AH_OFF  0
#define AL_OFF  8192
#define WH_OFF  16384
#define WL_OFF  20480
#define BIAS_OFF   49152
#define SCALE_OFF  49408
#define SHIFT_OFF  50432
#define SSUM_OFF   51456
#define SSQ_OFF    52480
#define GSMEM      53504

template<int MODE, int STATS, int ABF16, int WB>
__global__ void __launch_bounds__(256, 2)
gemm_mma(const float* __restrict__ A1, const float* __restrict__ A2,
         const float* __restrict__ D2,
         const __nv_bfloat16* __restrict__ A1h, const __nv_bfloat16* __restrict__ A1l,
         const __nv_bfloat16* __restrict__ Whi, const __nv_bfloat16* __restrict__ Wlo,
         const float* __restrict__ bias, float* __restrict__ C,
         __nv_bfloat16* __restrict__ Chi, __nv_bfloat16* __restrict__ Clo)
{
    extern __shared__ __align__(1024) char smem[];
    const uint32_t sb = smem_u32(smem);
    const int tid  = threadIdx.x;
    const int lane = tid & 31;
    const int wid  = tid >> 5;
    const int n0 = blockIdx.x * BM;
    const int c0 = blockIdx.y * BNT;

    float* s_bias  = (float*)(smem + BIAS_OFF);
    float* s_scale = (float*)(smem + SCALE_OFF);
    float* s_shift = (float*)(smem + SHIFT_OFF);
    float* s_sum   = (float*)(smem + SSUM_OFF);
    float* s_sq    = (float*)(smem + SSQ_OFF);

    if (tid < BNT) s_bias[tid] = bias[c0 + tid];
    if (MODE != 0) { s_scale[tid] = g_scale[tid]; s_shift[tid] = g_shift[tid]; }
    __syncthreads();

    // ---- A fetch, fp32 path (MODE transform) ----
    const int lr = tid >> 3;
    const int lc = (tid & 7) << 2;
    float4 ra[4];
    auto fetchA = [&](int kc) {
        #pragma unroll
        for (int i = 0; i < 4; ++i) {
            const size_t gof = (size_t)(n0 + lr + i*32) * DD + kc + lc;
            float4 v = __ldg((const float4*)(A1 + gof));
            if (MODE == 1) {
                float4 v2 = __ldg((const float4*)(A2 + gof));
                v.x -= v2.x; v.y -= v2.y; v.z -= v2.z; v.w -= v2.w;
            }
            if (MODE != 0) {
                const int cc = kc + lc;
                v.x = fmaxf(fmaf(v.x, s_scale[cc+0], s_shift[cc+0]), 0.f);
                v.y = fmaxf(fmaf(v.y, s_scale[cc+1], s_shift[cc+1]), 0.f);
                v.z = fmaxf(fmaf(v.z, s_scale[cc+2], s_shift[cc+2]), 0.f);
                v.w = fmaxf(fmaf(v.w, s_scale[cc+3], s_shift[cc+3]), 0.f);
            }
            ra[i] = v;
        }
    };
    auto storeA = [&](int stg) {
        char* base = smem + stg * ST_SZ;
        #pragma unroll
        for (int i = 0; i < 4; ++i) {
            float4 v = ra[i];
            float r0, r1, r2, r3;
            unsigned int h01 = bf_hi(v.x, r0) | ((unsigned int)bf_hi(v.y, r1) << 16);
            unsigned int h23 = bf_hi(v.z, r2) | ((unsigned int)bf_hi(v.w, r3) << 16);
            unsigned int l01 = bf_rn(r0) | ((unsigned int)bf_rn(r1) << 16);
            unsigned int l23 = bf_rn(r2) | ((unsigned int)bf_rn(r3) << 16);
            const uint32_t so = swz((uint32_t)((lr + i*32) * 64 + lc * 2));
            *(uint2*)(base + AH_OFF + so) = make_uint2(h01, h23);
            *(uint2*)(base + AL_OFF + so) = make_uint2(l01, l23);
        }
    };
    // ---- A fetch, bf16 path: straight cp.async of pre-split hi/lo ----
    auto asyncA = [&](int kc, int stg) {
        const int row = tid >> 1;
        const int c2  = (tid & 1) * 2;
        const __nv_bfloat16* ph = A1h + (size_t)(n0 + row) * DD + kc;
        const __nv_bfloat16* pl = A1l + (size_t)(n0 + row) * DD + kc;
        #pragma unroll
        for (int c = 0; c < 2; ++c) {
            const int cc = c2 + c;
            const uint32_t so = swz((uint32_t)(row * 64 + cc * 16));
            cpasync16(sb + stg*ST_SZ + AH_OFF + so, ph + cc*8);
            cpasync16(sb + stg*ST_SZ + AL_OFF + so, pl + cc*8);
        }
    };
    // ---- W fetch via cp.async ----
    const int wrow = tid >> 2;
    const int wch  = tid & 3;
    auto asyncW = [&](int kc, int stg) {
        const uint32_t so = swz((uint32_t)(wrow * 64 + wch * 16));
        cpasync16(sb + stg*ST_SZ + WH_OFF + so, Whi + (size_t)(c0 + wrow) * DD + kc + wch*8);
        cpasync16(sb + stg*ST_SZ + WL_OFF + so, Wlo + (size_t)(c0 + wrow) * DD + kc + wch*8);
    };

    // ---- per-warp mma state ----
    const int mw   = wid >> 1;
    const int nw   = wid & 1;
    const int moff = mw * 32;
    const int noff = nw * 32;
    const uint32_t arow   = moff + (lane & 15);
    const uint32_t acol16 = (uint32_t)(lane >> 4) * 16;
    const uint32_t brow   = noff + (lane & 7) + ((lane >> 1) & 8);
    const uint32_t bcol16 = (uint32_t)((lane >> 3) & 1) * 16;

    float d[2][4][4];
    #pragma unroll
    for (int i = 0; i < 2; ++i)
        #pragma unroll
        for (int j = 0; j < 4; ++j)
            #pragma unroll
            for (int q = 0; q < 4; ++q) d[i][j][q] = 0.f;

    // ---- prologue: chunk 0 into stage 0 ----
    if (ABF16) {
        asyncA(0, 0);
        asyncW(0, 0);
        asm volatile("cp.async.commit_group;");
        asm volatile("cp.async.wait_group 0;");
    } else {
        fetchA(0);
        asyncW(0, 0);
        asm volatile("cp.async.commit_group;");
        storeA(0);
        asm volatile("cp.async.wait_group 0;");
    }
    __syncthreads();

    #pragma unroll 1
    for (int ch = 0; ch < NCH; ++ch) {
        const int cur = ch & 1;

        // prefetch chunk ch+1 into stage cur^1 (readers retired by prev barrier)
        if (ch + 1 < NCH) {
            if (ABF16) {
                asyncA((ch+1) * BK, cur ^ 1);
            } else {
                fetchA((ch+1) * BK);
            }
            asyncW((ch+1) * BK, cur ^ 1);
            asm volatile("cp.async.commit_group;");
        }

        const uint32_t aBH = sb + cur*ST_SZ + AH_OFF;
        const uint32_t aBL = sb + cur*ST_SZ + AL_OFF;
        const uint32_t wBH = sb + cur*ST_SZ + WH_OFF;
        const uint32_t wBL = sb + cur*ST_SZ + WL_OFF;

        #pragma unroll
        for (int ks = 0; ks < 2; ++ks) {
            uint32_t ah[2][4], al[2][4];
            #pragma unroll
            for (int mt = 0; mt < 2; ++mt) {
                const uint32_t ao = swz((arow + mt*16) * 64 + ks*32 + acol16);
                ldsm4(ah[mt][0], ah[mt][1], ah[mt][2], ah[mt][3], aBH + ao);
                ldsm4(al[mt][0], al[mt][1], al[mt][2], al[mt][3], aBL + ao);
            }
            #pragma unroll
            for (int ng = 0; ng < 2; ++ng) {
                const uint32_t bo = swz((brow + ng*16) * 64 + ks*32 + bcol16);
                uint32_t bh0, bh1, bh2, bh3, bl0, bl1, bl2, bl3;
                ldsm4(bh0, bh1, bh2, bh3, wBH + bo);
                ldsm4(bl0, bl1, bl2, bl3, wBL + bo);
                #pragma unroll
                for (int mt = 0; mt < 2; ++mt) {
                    mma_bf16(d[mt][ng*2+0], ah[mt], bh0, bh1);
                    mma_bf16(d[mt][ng*2+0], ah[mt], bl0, bl1);
                    mma_bf16(d[mt][ng*2+0], al[mt], bh0, bh1);
                    mma_bf16(d[mt][ng*2+1], ah[mt], bh2, bh3);
                    mma_bf16(d[mt][ng*2+1], ah[mt], bl2, bl3);
                    mma_bf16(d[mt][ng*2+1], al[mt], bh2, bh3);
                }
            }
        }

        if (ch + 1 < NCH) {
            if (!ABF16) storeA(cur ^ 1);
            asm volatile("cp.async.wait_group 0;");
            __syncthreads();
        }
    }

    // ---- epilogue ----
    const int erow = lane >> 2;
    const int ecol = (lane & 3) * 2;
    float cs[8], cq[8];
    #pragma unroll
    for (int i = 0; i < 8; ++i) { cs[i] = 0.f; cq[i] = 0.f; }

    #pragma unroll
    for (int mt = 0; mt < 2; ++mt) {
        #pragma unroll
        for (int nt = 0; nt < 4; ++nt) {
            const int col = noff + nt*8 + ecol;
            const float b0 = s_bias[col], b1 = s_bias[col + 1];
            const int row = n0 + moff + mt*16 + erow;
            float* base = C + (size_t)row * DD + c0 + col;
            const float v00 = d[mt][nt][0] + b0, v01 = d[mt][nt][1] + b1;
            const float v10 = d[mt][nt][2] + b0, v11 = d[mt][nt][3] + b1;
            *(float2*)base          = make_float2(v00, v01);
            *(float2*)(base + 8*DD) = make_float2(v10, v11);
            if (WB) {
                float rr;
                const unsigned short h00 = bf_hi(v00, rr); const unsigned short l00 = bf_rn(rr);
                const unsigned short h01 = bf_hi(v01, rr); const unsigned short l01 = bf_rn(rr);
                const unsigned short h10 = bf_hi(v10, rr); const unsigned short l10 = bf_rn(rr);
                const unsigned short h11 = bf_hi(v11, rr); const unsigned short l11 = bf_rn(rr);
                *(ushort2*)(Chi + (size_t)row * DD + c0 + col)       = make_ushort2(h00, h01);
                *(ushort2*)(Clo + (size_t)row * DD + c0 + col)       = make_ushort2(l00, l01);
                *(ushort2*)(Chi + (size_t)(row + 8) * DD + c0 + col) = make_ushort2(h10, h11);
                *(ushort2*)(Clo + (size_t)(row + 8) * DD + c0 + col) = make_ushort2(l10, l11);
            }
            if (STATS) {
                float w00 = v00, w01 = v01, w10 = v10, w11 = v11;
                if (STATS == 2) {
                    const float* qb = D2 + (size_t)row * DD + c0 + col;
                    float2 qa = *(const float2*)qb;
                    float2 qc = *(const float2*)(qb + 8*DD);
                    w00 -= qa.x; w01 -= qa.y; w10 -= qc.x; w11 -= qc.y;
                }
                cs[nt*2+0] += w00 + w10;  cq[nt*2+0] += w00*w00 + w10*w10;
                cs[nt*2+1] += w01 + w11;  cq[nt*2+1] += w01*w01 + w11*w11;
            }
        }
    }

    if (STATS) {
        #pragma unroll
        for (int o = 4; o <= 16; o <<= 1) {
            #pragma unroll
            for (int i = 0; i < 8; ++i) {
                cs[i] += __shfl_xor_sync(0xffffffffu, cs[i], o);
                cq[i] += __shfl_xor_sync(0xffffffffu, cq[i], o);
            }
        }
        __syncthreads();
        if (lane < 4) {
            #pragma unroll
            for (int nt = 0; nt < 4; ++nt) {
                #pragma unroll
                for (int q = 0; q < 2; ++q) {
                    const int c = noff + nt*8 + lane*2 + q;
                    s_sum[mw*64 + c] = cs[nt*2+q];
                    s_sq [mw*64 + c] = cq[nt*2+q];
                }
            }
        }
        __syncthreads();
        if (tid < 64) {
            float s = s_sum[tid] + s_sum[64+tid] + s_sum[128+tid] + s_sum[192+tid];
            float q = s_sq [tid] + s_sq [64+tid] + s_sq [128+tid] + s_sq [192+tid];
            g_psum[blockIdx.x][0][c0 + tid] = s;
            g_psum[blockIdx.x][1][c0 + tid] = q;
        }
    }
}

// ===========================================================================
// stats reduce: 512 CTA partials -> 32 -> scale/shift
// ===========================================================================
__global__ void stats_mid_k()
{
    const int r = blockIdx.x;
    const int t = threadIdx.x;
    float s = 0.f, q = 0.f;
    #pragma unroll
    for (int i = 0; i < 16; ++i) {
        s += g_psum[r*16 + i][0][t];
        q += g_psum[r*16 + i][1][t];
    }
    g_pmid[r][0][t] = s;
    g_pmid[r][1][t] = q;
}

__global__ void stats_final_k(const float* __restrict__ gamma, const float* __restrict__ beta)
{
    const int t = threadIdx.x;
    float s = 0.f, q = 0.f;
    #pragma unroll
    for (int c = 0; c < 32; ++c) { s += g_pmid[c][0][t]; q += g_pmid[c][1][t]; }
    const float inv = 1.f / (float)NROWS;
    const float mean = s * inv;
    const float var  = q * inv - mean * mean;
    const float sc   = rsqrtf(var + EPS) * gamma[t];
    g_scale[t] = sc;
    g_shift[t] = beta[t] - mean * sc;
}

// ===========================================================================
// Online softmax over S fused with V-weighted sum, float4-vectorized.
// ===========================================================================
__global__ void softmax_part_k(const float* __restrict__ W2, const float* __restrict__ V)
{
    __shared__ float4 smm[4][64], sml[4][64], sma[4][64];
    const int b  = blockIdx.x;
    const int sc = blockIdx.y;
    const int ql = threadIdx.x & 63;
    const int sg = threadIdx.x >> 6;
    const size_t stride = (size_t)BB * DD;
    size_t off = (size_t)(sc*128 + sg) * stride + (size_t)b * DD + ql*4;

    float4 m = make_float4(-INFINITY,-INFINITY,-INFINITY,-INFINITY);
    float4 l = make_float4(0.f,0.f,0.f,0.f);
    float4 a = make_float4(0.f,0.f,0.f,0.f);
    #pragma unroll 4
    for (int i = 0; i < 32; ++i) {
        const float4 w  = *(const float4*)(W2 + off);
        const float4 vv = *(const float4*)(V  + off);
        float4 nm;
        nm.x = fmaxf(m.x, w.x); nm.y = fmaxf(m.y, w.y);
        nm.z = fmaxf(m.z, w.z); nm.w = fmaxf(m.w, w.w);
        const float e1x = expf(m.x - nm.x), e2x = expf(w.x - nm.x);
        const float e1y = expf(m.y - nm.y), e2y = expf(w.y - nm.y);
        const float e1z = expf(m.z - nm.z), e2z = expf(w.z - nm.z);
        const float e1w = expf(m.w - nm.w), e2w = expf(w.w - nm.w);
        l.x = l.x*e1x + e2x;  a.x = a.x*e1x + e2x*vv.x;
        l.y = l.y*e1y + e2y;  a.y = a.y*e1y + e2y*vv.y;
        l.z = l.z*e1z + e2z;  a.z = a.z*e1z + e2z*vv.z;
        l.w = l.w*e1w + e2w;  a.w = a.w*e1w + e2w*vv.w;
        m = nm;
        off += 4 * stride;
    }
    smm[sg][ql] = m; sml[sg][ql] = l; sma[sg][ql] = a;
    __syncthreads();
    if (sg == 0) {
        float4 M = smm[0][ql], L = sml[0][ql], A = sma[0][ql];
        #pragma unroll
        for (int g = 1; g < 4; ++g) {
            const float4 m2 = smm[g][ql], l2 = sml[g][ql], a2 = sma[g][ql];
            float4 NM;
            NM.x = fmaxf(M.x, m2.x); NM.y = fmaxf(M.y, m2.y);
            NM.z = fmaxf(M.z, m2.z); NM.w = fmaxf(M.w, m2.w);
            const float p1x = expf(M.x-NM.x), p2x = expf(m2.x-NM.x);
            const float p1y = expf(M.y-NM.y), p2y = expf(m2.y-NM.y);
            const float p1z = expf(M.z-NM.z), p2z = expf(m2.z-NM.z);
            const float p1w = expf(M.w-NM.w), p2w = expf(m2.w-NM.w);
            L.x = L.x*p1x + l2.x*p2x;  A.x = A.x*p1x + a2.x*p2x;
            L.y = L.y*p1y + l2.y*p2y;  A.y = A.y*p1y + a2.y*p2y;
            L.z = L.z*p1z + l2.z*p2z;  A.z = A.z*p1z + a2.z*p2z;
            L.w = L.w*p1w + l2.w*p2w;  A.w = A.w*p1w + a2.w*p2w;
            M = NM;
        }
        *(float4*)&g_sm_m[sc][b][ql*4] = M;
        *(float4*)&g_sm_l[sc][b][ql*4] = L;
        *(float4*)&g_sm_a[sc][b][ql*4] = A;
    }
}

__global__ void softmax_final_k(int head)
{
    const int b = blockIdx.x;
    const int d = threadIdx.x;
    float M = -INFINITY;
    #pragma unroll
    for (int c = 0; c < 16; ++c) M = fmaxf(M, g_sm_m[c][b][d]);
    float L = 0.f, A = 0.f;
    #pragma unroll
    for (int c = 0; c < 16; ++c) {
        const float e = expf(g_sm_m[c][b][d] - M);
        L += g_sm_l[c][b][d] * e;
        A += g_sm_a[c][b][d] * e;
    }
    g_headout[b][head * DD + d] = A / L;
}

// ===========================================================================
// Final tiny MLP
// ===========================================================================
template<bool RELU, int E>
__global__ void mlp_k(const float* __restrict__ X, const float* __restrict__ W,
                      const float* __restrict__ bias, float* __restrict__ out)
{
    __shared__ float sw[E];
    __shared__ float red[4];
    const int j = blockIdx.x;
    const int t = threadIdx.x;
    for (int e = t; e < E; e += 128) sw[e] = W[(size_t)j * E + e];
    __syncthreads();
    for (int b = 0; b < BB; ++b) {
        float p = 0.f;
        for (int e = t; e < E; e += 128) p += X[(size_t)b * E + e] * sw[e];
        #pragma unroll
        for (int o = 16; o; o >>= 1) p += __shfl_xor_sync(0xffffffffu, p, o);
        if ((t & 31) == 0) red[t >> 5] = p;
        __syncthreads();
        if (t == 0) {
            float r = red[0] + red[1] + red[2] + red[3] + bias[j];
            if (RELU) r = fmaxf(r, 0.f);
            out[(size_t)b * DD + j] = r;
        }
        __syncthreads();
    }
}

// ===========================================================================
extern "C" void kernel_launch(void* const* d_in, const int* in_sizes, int n_in,
                              void* d_out, int out_size)
{
    (void)in_sizes; (void)n_in; (void)out_size;
    const float* q   = (const float*)d_in[0];
    const float* k   = (const float*)d_in[1];
    const float* v   = (const float*)d_in[2];
    const float* wq  = (const float*)d_in[3];
    const float* bq  = (const float*)d_in[4];
    const float* wk  = (const float*)d_in[5];
    const float* bk  = (const float*)d_in[6];
    const float* wv  = (const float*)d_in[7];
    const float* bv  = (const float*)d_in[8];
    const float* g1  = (const float*)d_in[9];
    const float* be1 = (const float*)d_in[10];
    const float* wl1 = (const float*)d_in[11];
    const float* bl1 = (const float*)d_in[12];
    const float* g2  = (const float*)d_in[13];
    const float* be2 = (const float*)d_in[14];
    const float* wl2 = (const float*)d_in[15];
    const float* bl2 = (const float*)d_in[16];
    const float* mw0 = (const float*)d_in[17];
    const float* mb0 = (const float*)d_in[18];
    const float* mw1 = (const float*)d_in[19];
    const float* mb1 = (const float*)d_in[20];
    const float* mw2 = (const float*)d_in[21];
    const float* mb2 = (const float*)d_in[22];
    float* out = (float*)d_out;

    float *buf = nullptr, *headout = nullptr, *m0 = nullptr, *m1 = nullptr;
    __nv_bfloat16 *whi = nullptr, *wlo = nullptr, *ahi = nullptr, *alo = nullptr;
    cudaGetSymbolAddress((void**)&buf,     g_buf);
    cudaGetSymbolAddress((void**)&headout, g_headout);
    cudaGetSymbolAddress((void**)&m0,      g_mlp0);
    cudaGetSymbolAddress((void**)&m1,      g_mlp1);
    cudaGetSymbolAddress((void**)&whi,     g_whi);
    cudaGetSymbolAddress((void**)&wlo,     g_wlo);
    cudaGetSymbolAddress((void**)&ahi,     g_ahi);
    cudaGetSymbolAddress((void**)&alo,     g_alo);

    static bool attr_done = false;
    if (!attr_done) {
        cudaFuncSetAttribute(gemm_mma<0,0,1,1>, cudaFuncAttributeMaxDynamicSharedMemorySize, GSMEM);
        cudaFuncSetAttribute(gemm_mma<0,2,1,1>, cudaFuncAttributeMaxDynamicSharedMemorySize, GSMEM);
        cudaFuncSetAttribute(gemm_mma<1,1,0,0>, cudaFuncAttributeMaxDynamicSharedMemorySize, GSMEM);
        cudaFuncSetAttribute(gemm_mma<2,0,0,0>, cudaFuncAttributeMaxDynamicSharedMemorySize, GSMEM);
        attr_done = true;
    }

    const size_t SZ = (size_t)NROWS * DD;
    dim3 ggrid(NROWS / BM, DD / BNT);     // (512, 4)

    wconv_k<<<(5 * HH * DD * DD) / 256, 256>>>(wq, wk, wv, wl1, wl2);
    insplit_k<<<dim3(NROWS * DD / 1024, 3), 256>>>(q, k, v);

    for (int h = 0; h < HH; ++h) {
        float* Qn = buf + 0 * SZ;
        float* Kn = buf + 2 * SZ;
        float* Vn = buf + 4 * SZ;
        float* T1 = buf + 6 * SZ;
        float* T2 = buf + 7 * SZ;
        const int rb = ((h + 1) & 1) * 3;     // bf16 read slots (prev head / input)
        const int wb = (h & 1) * 3;           // bf16 write slots (this head)
        const __nv_bfloat16* Qah = ahi + (size_t)(rb+0) * SZ; const __nv_bfloat16* Qal = alo + (size_t)(rb+0) * SZ;
        const __nv_bfloat16* Kah = ahi + (size_t)(rb+1) * SZ; const __nv_bfloat16* Kal = alo + (size_t)(rb+1) * SZ;
        const __nv_bfloat16* Vah = ahi + (size_t)(rb+2) * SZ; const __nv_bfloat16* Val = alo + (size_t)(rb+2) * SZ;
        __nv_bfloat16* Qch = ahi + (size_t)(wb+0) * SZ; __nv_bfloat16* Qcl = alo + (size_t)(wb+0) * SZ;
        __nv_bfloat16* Kch = ahi + (size_t)(wb+1) * SZ; __nv_bfloat16* Kcl = alo + (size_t)(wb+1) * SZ;
        __nv_bfloat16* Vch = ahi + (size_t)(wb+2) * SZ; __nv_bfloat16* Vcl = alo + (size_t)(wb+2) * SZ;
        const size_t wsz = (size_t)DD * DD;
        const __nv_bfloat16* Wq_h = whi + (h*5 + 0) * wsz; const __nv_bfloat16* Wq_l = wlo + (h*5 + 0) * wsz;
        const __nv_bfloat16* Wk_h = whi + (h*5 + 1) * wsz; const __nv_bfloat16* Wk_l = wlo + (h*5 + 1) * wsz;
        const __nv_bfloat16* Wv_h = whi + (h*5 + 2) * wsz; const __nv_bfloat16* Wv_l = wlo + (h*5 + 2) * wsz;
        const __nv_bfloat16* W1_h = whi + (h*5 + 3) * wsz; const __nv_bfloat16* W1_l = wlo + (h*5 + 3) * wsz;
        const __nv_bfloat16* W2_h = whi + (h*5 + 4) * wsz; const __nv_bfloat16* W2_l = wlo + (h*5 + 4) * wsz;

        // projections (A pre-split bf16, write bf16 copies); K fuses BN1 diff-stats
        gemm_mma<0,0,1,1><<<ggrid, 256, GSMEM>>>(nullptr, nullptr, nullptr, Qah, Qal, Wq_h, Wq_l, bq + h*DD, Qn, Qch, Qcl);
        gemm_mma<0,2,1,1><<<ggrid, 256, GSMEM>>>(nullptr, nullptr, Qn,      Kah, Kal, Wk_h, Wk_l, bk + h*DD, Kn, Kch, Kcl);
        gemm_mma<0,0,1,1><<<ggrid, 256, GSMEM>>>(nullptr, nullptr, nullptr, Vah, Val, Wv_h, Wv_l, bv + h*DD, Vn, Vch, Vcl);
        stats_mid_k<<<32, 256>>>();
        stats_final_k<<<1, 256>>>(g1 + h*DD, be1 + h*DD);

        // relu(bn1(K-Q)) @ wl1^T + bl1, fused self-stats for BN2
        gemm_mma<1,1,0,0><<<ggrid, 256, GSMEM>>>(Kn, Qn, nullptr, nullptr, nullptr, W1_h, W1_l, bl1 + h*DD, T1, nullptr, nullptr);
        stats_mid_k<<<32, 256>>>();
        stats_final_k<<<1, 256>>>(g2 + h*DD, be2 + h*DD);

        // relu(bn2(T1)) @ wl2^T + bl2
        gemm_mma<2,0,0,0><<<ggrid, 256, GSMEM>>>(T1, nullptr, nullptr, nullptr, nullptr, W2_h, W2_l, bl2 + h*DD, T2, nullptr, nullptr);

        softmax_part_k<<<dim3(BB, 16), 256>>>(T2, Vn);
        softmax_final_k<<<BB, DD>>>(h);
    }

    mlp_k<true,  HH*DD><<<DD, 128>>>(headout, mw0, mb0, m0);
    mlp_k<true,  DD   ><<<DD, 128>>>(m0,      mw1, mb1, m1);
    mlp_k<false, DD   ><<<DD, 128>>>(m1,      mw2, mb2, out);
}

// round 10
// speedup vs baseline: 1.1824x; 1.1824x over previous
#include <cuda_runtime.h>
#include <cuda_bf16.h>
#include <math.h>
#include <stdint.h>

#define SS 2048
#define BB 32
#define DD 256
#define HH 4
#define NROWS (SS*BB)          // 65536
#define EPS 1e-5f

// ---------------- scratch (static device globals; no allocations) ----------
__device__ float g_buf[(size_t)8 * NROWS * DD];        // ping/pong Q,K,V + T1,T2
__device__ float g_psum[512][2][DD];                   // per-CTA-row stats partials
__device__ float g_pmid[32][2][DD];
__device__ float g_scale[DD];
__device__ float g_shift[DD];
__device__ float g_sm_m[16][BB][DD];
__device__ float g_sm_l[16][BB][DD];
__device__ float g_sm_a[16][BB][DD];
__device__ float g_headout[BB][HH*DD];
__device__ float g_mlp0[BB][DD];
__device__ float g_mlp1[BB][DD];
__device__ __nv_bfloat16 g_whi[20][DD*DD];             // 5 weights x 4 heads, hi
__device__ __nv_bfloat16 g_wlo[20][DD*DD];             // lo (fp32 remainder)

// ======================= helpers ==========================================
__device__ __forceinline__ uint32_t smem_u32(const void* p) {
    uint32_t a;
    asm("{ .reg .u64 t; cvta.to.shared.u64 t, %1; cvt.u32.u64 %0, t; }"
        : "=r"(a) : "l"(p));
    return a;
}
__device__ __forceinline__ uint32_t swz(uint32_t off) {   // 64B-row swizzle
    return off ^ ((off >> 3) & 0x30);
}
__device__ __forceinline__ void ldsm4(uint32_t& r0, uint32_t& r1,
                                      uint32_t& r2, uint32_t& r3, uint32_t addr) {
    asm volatile("ldmatrix.sync.aligned.m8n8.x4.shared.b16 {%0,%1,%2,%3}, [%4];"
                 : "=r"(r0), "=r"(r1), "=r"(r2), "=r"(r3) : "r"(addr));
}
__device__ __forceinline__ void mma_bf16(float* d, const uint32_t* a,
                                         uint32_t b0, uint32_t b1) {
    asm volatile(
        "mma.sync.aligned.m16n8k16.row.col.f32.bf16.bf16.f32 "
        "{%0,%1,%2,%3},{%4,%5,%6,%7},{%8,%9},{%0,%1,%2,%3};"
        : "+f"(d[0]), "+f"(d[1]), "+f"(d[2]), "+f"(d[3])
        : "r"(a[0]), "r"(a[1]), "r"(a[2]), "r"(a[3]), "r"(b0), "r"(b1));
}
__device__ __forceinline__ void cpasync16(uint32_t dst, const void* src) {
    asm volatile("cp.async.ca.shared.global [%0], [%1], 16;" :: "r"(dst), "l"(src));
}
__device__ __forceinline__ unsigned short bf_hi(float x, float& rem) {
    __nv_bfloat16 h = __float2bfloat16_rn(x);
    rem = x - __bfloat162float(h);
    return __bfloat16_as_ushort(h);
}
__device__ __forceinline__ unsigned short bf_rn(float x) {
    return __bfloat16_as_ushort(__float2bfloat16_rn(x));
}

// ===========================================================================
// Weight pre-split: fp32 -> bf16 hi/lo.  slot = head*5 + {wq,wk,wv,wl1,wl2}
// ===========================================================================
__global__ void wconv_k(const float* __restrict__ wq, const float* __restrict__ wk,
                        const float* __restrict__ wv, const float* __restrict__ wl1,
                        const float* __restrict__ wl2)
{
    int idx = blockIdx.x * blockDim.x + threadIdx.x;
    int t = idx >> 18;
    int r = idx & 0x3FFFF;
    const float* src = (t == 0 ? wq : t == 1 ? wk : t == 2 ? wv : t == 3 ? wl1 : wl2);
    float x = src[r];
    int h = r >> 16;
    int e = r & 0xFFFF;
    int slot = h * 5 + t;
    float rem;
    unsigned short hi = bf_hi(x, rem);
    g_whi[slot][e] = __ushort_as_bfloat16(hi);
    g_wlo[slot][e] = __ushort_as_bfloat16(bf_rn(rem));
}

// ===========================================================================
// HMMA GEMM (round-6 design, best measured): C = f(A) @ W^T + bias
//   MODE 0: identity;  MODE 1: relu((A1-A2)*scale+shift);  MODE 2: relu(A1*scale+shift)
//   STATS 0: none; 1: per-col sum/sumsq of output; 2: of (output - D2)
// CTA 128x64, 8 warps (4M x 2N, 32x32 warp tiles), 2-stage cp.async pipeline.
// Writes to a stage only after the barrier retiring its readers.
// ===========================================================================
#define BM 128
#define BNT 64
#define BK 32
#define NCH (DD/BK)            // 8

#define ST_SZ   24576          // per stage: Ah 8K, Al 8K, Wh 4K, Wl 4K
#define AH_OFF  0
#define AL_OFF  8192
#define WH_OFF  16384
#define WL_OFF  20480
#define BIAS_OFF   49152
#define SCALE_OFF  49408
#define SHIFT_OFF  50432
#define SSUM_OFF   51456
#define SSQ_OFF    52480
#define GSMEM      53504

template<int MODE, int STATS>
__global__ void __launch_bounds__(256, 2)
gemm_mma(const float* __restrict__ A1, const float* __restrict__ A2,
         const float* __restrict__ D2,
         const __nv_bfloat16* __restrict__ Whi, const __nv_bfloat16* __restrict__ Wlo,
         const float* __restrict__ bias, float* __restrict__ C)
{
    extern __shared__ __align__(1024) char smem[];
    const uint32_t sb = smem_u32(smem);
    const int tid  = threadIdx.x;
    const int lane = tid & 31;
    const int wid  = tid >> 5;
    const int n0 = blockIdx.x * BM;
    const int c0 = blockIdx.y * BNT;

    float* s_bias  = (float*)(smem + BIAS_OFF);
    float* s_scale = (float*)(smem + SCALE_OFF);
    float* s_shift = (float*)(smem + SHIFT_OFF);
    float* s_sum   = (float*)(smem + SSUM_OFF);
    float* s_sq    = (float*)(smem + SSQ_OFF);

    if (tid < BNT) s_bias[tid] = bias[c0 + tid];
    if (MODE != 0) { s_scale[tid] = g_scale[tid]; s_shift[tid] = g_shift[tid]; }
    __syncthreads();

    // ---- A fetch (fp32 + transform) ----
    const int lr = tid >> 3;
    const int lc = (tid & 7) << 2;
    float4 ra[4];
    auto fetchA = [&](int kc) {
        #pragma unroll
        for (int i = 0; i < 4; ++i) {
            const size_t gof = (size_t)(n0 + lr + i*32) * DD + kc + lc;
            float4 v = __ldg((const float4*)(A1 + gof));
            if (MODE == 1) {
                float4 v2 = __ldg((const float4*)(A2 + gof));
                v.x -= v2.x; v.y -= v2.y; v.z -= v2.z; v.w -= v2.w;
            }
            if (MODE != 0) {
                const int cc = kc + lc;
                v.x = fmaxf(fmaf(v.x, s_scale[cc+0], s_shift[cc+0]), 0.f);
                v.y = fmaxf(fmaf(v.y, s_scale[cc+1], s_shift[cc+1]), 0.f);
                v.z = fmaxf(fmaf(v.z, s_scale[cc+2], s_shift[cc+2]), 0.f);
                v.w = fmaxf(fmaf(v.w, s_scale[cc+3], s_shift[cc+3]), 0.f);
            }
            ra[i] = v;
        }
    };
    auto storeA = [&](int stg) {
        char* base = smem + stg * ST_SZ;
        #pragma unroll
        for (int i = 0; i < 4; ++i) {
            float4 v = ra[i];
            float r0, r1, r2, r3;
            unsigned int h01 = bf_hi(v.x, r0) | ((unsigned int)bf_hi(v.y, r1) << 16);
            unsigned int h23 = bf_hi(v.z, r2) | ((unsigned int)bf_hi(v.w, r3) << 16);
            unsigned int l01 = bf_rn(r0) | ((unsigned int)bf_rn(r1) << 16);
            unsigned int l23 = bf_rn(r2) | ((unsigned int)bf_rn(r3) << 16);
            const uint32_t so = swz((uint32_t)((lr + i*32) * 64 + lc * 2));
            *(uint2*)(base + AH_OFF + so) = make_uint2(h01, h23);
            *(uint2*)(base + AL_OFF + so) = make_uint2(l01, l23);
        }
    };
    // ---- W fetch via cp.async (64 rows x 32 bf16, hi & lo) ----
    const int wrow = tid >> 2;
    const int wch  = tid & 3;
    auto asyncW = [&](int kc, int stg) {
        const uint32_t so = swz((uint32_t)(wrow * 64 + wch * 16));
        cpasync16(sb + stg*ST_SZ + WH_OFF + so, Whi + (size_t)(c0 + wrow) * DD + kc + wch*8);
        cpasync16(sb + stg*ST_SZ + WL_OFF + so, Wlo + (size_t)(c0 + wrow) * DD + kc + wch*8);
    };

    // ---- per-warp mma state ----
    const int mw   = wid >> 1;
    const int nw   = wid & 1;
    const int moff = mw * 32;
    const int noff = nw * 32;
    const uint32_t arow   = moff + (lane & 15);
    const uint32_t acol16 = (uint32_t)(lane >> 4) * 16;
    const uint32_t brow   = noff + (lane & 7) + ((lane >> 1) & 8);
    const uint32_t bcol16 = (uint32_t)((lane >> 3) & 1) * 16;

    float d[2][4][4];
    #pragma unroll
    for (int i = 0; i < 2; ++i)
        #pragma unroll
        for (int j = 0; j < 4; ++j)
            #pragma unroll
            for (int q = 0; q < 4; ++q) d[i][j][q] = 0.f;

    // ---- prologue: chunk 0 into stage 0, fully ready before loop ----
    fetchA(0);
    asyncW(0, 0);
    asm volatile("cp.async.commit_group;");
    storeA(0);
    asm volatile("cp.async.wait_group 0;");
    __syncthreads();

    #pragma unroll 1
    for (int ch = 0; ch < NCH; ++ch) {
        const int cur = ch & 1;

        // Prefetch chunk ch+1 into stage cur^1 (readers retired by prev barrier)
        if (ch + 1 < NCH) {
            fetchA((ch+1) * BK);
            asyncW((ch+1) * BK, cur ^ 1);
            asm volatile("cp.async.commit_group;");
        }

        const uint32_t aBH = sb + cur*ST_SZ + AH_OFF;
        const uint32_t aBL = sb + cur*ST_SZ + AL_OFF;
        const uint32_t wBH = sb + cur*ST_SZ + WH_OFF;
        const uint32_t wBL = sb + cur*ST_SZ + WL_OFF;

        #pragma unroll
        for (int ks = 0; ks < 2; ++ks) {
            uint32_t ah[2][4], al[2][4];
            #pragma unroll
            for (int mt = 0; mt < 2; ++mt) {
                const uint32_t ao = swz((arow + mt*16) * 64 + ks*32 + acol16);
                ldsm4(ah[mt][0], ah[mt][1], ah[mt][2], ah[mt][3], aBH + ao);
                ldsm4(al[mt][0], al[mt][1], al[mt][2], al[mt][3], aBL + ao);
            }
            #pragma unroll
            for (int ng = 0; ng < 2; ++ng) {
                const uint32_t bo = swz((brow + ng*16) * 64 + ks*32 + bcol16);
                uint32_t bh0, bh1, bh2, bh3, bl0, bl1, bl2, bl3;
                ldsm4(bh0, bh1, bh2, bh3, wBH + bo);
                ldsm4(bl0, bl1, bl2, bl3, wBL + bo);
                #pragma unroll
                for (int mt = 0; mt < 2; ++mt) {
                    mma_bf16(d[mt][ng*2+0], ah[mt], bh0, bh1);
                    mma_bf16(d[mt][ng*2+0], ah[mt], bl0, bl1);
                    mma_bf16(d[mt][ng*2+0], al[mt], bh0, bh1);
                    mma_bf16(d[mt][ng*2+1], ah[mt], bh2, bh3);
                    mma_bf16(d[mt][ng*2+1], ah[mt], bl2, bl3);
                    mma_bf16(d[mt][ng*2+1], al[mt], bh2, bh3);
                }
            }
        }

        if (ch + 1 < NCH) {
            storeA(cur ^ 1);
            asm volatile("cp.async.wait_group 0;");
            __syncthreads();
        }
    }

    // ---- epilogue: bias add, store, optional per-column stats ----
    const int erow = lane >> 2;
    const int ecol = (lane & 3) * 2;
    float cs[8], cq[8];
    #pragma unroll
    for (int i = 0; i < 8; ++i) { cs[i] = 0.f; cq[i] = 0.f; }

    #pragma unroll
    for (int mt = 0; mt < 2; ++mt) {
        #pragma unroll
        for (int nt = 0; nt < 4; ++nt) {
            const int col = noff + nt*8 + ecol;
            const float b0 = s_bias[col], b1 = s_bias[col + 1];
            const int row = n0 + moff + mt*16 + erow;
            float* base = C + (size_t)row * DD + c0 + col;
            const float v00 = d[mt][nt][0] + b0, v01 = d[mt][nt][1] + b1;
            const float v10 = d[mt][nt][2] + b0, v11 = d[mt][nt][3] + b1;
            *(float2*)base          = make_float2(v00, v01);
            *(float2*)(base + 8*DD) = make_float2(v10, v11);
            if (STATS) {
                float w00 = v00, w01 = v01, w10 = v10, w11 = v11;
                if (STATS == 2) {
                    const float* qb = D2 + (size_t)row * DD + c0 + col;
                    float2 qa = *(const float2*)qb;
                    float2 qc = *(const float2*)(qb + 8*DD);
                    w00 -= qa.x; w01 -= qa.y; w10 -= qc.x; w11 -= qc.y;
                }
                cs[nt*2+0] += w00 + w10;  cq[nt*2+0] += w00*w00 + w10*w10;
                cs[nt*2+1] += w01 + w11;  cq[nt*2+1] += w01*w01 + w11*w11;
            }
        }
    }

    if (STATS) {
        #pragma unroll
        for (int o = 4; o <= 16; o <<= 1) {
            #pragma unroll
            for (int i = 0; i < 8; ++i) {
                cs[i] += __shfl_xor_sync(0xffffffffu, cs[i], o);
                cq[i] += __shfl_xor_sync(0xffffffffu, cq[i], o);
            }
        }
        __syncthreads();
        if (lane < 4) {
            #pragma unroll
            for (int nt = 0; nt < 4; ++nt) {
                #pragma unroll
                for (int q = 0; q < 2; ++q) {
                    const int c = noff + nt*8 + lane*2 + q;
                    s_sum[mw*64 + c] = cs[nt*2+q];
                    s_sq [mw*64 + c] = cq[nt*2+q];
                }
            }
        }
        __syncthreads();
        if (tid < 64) {
            float s = s_sum[tid] + s_sum[64+tid] + s_sum[128+tid] + s_sum[192+tid];
            float q = s_sq [tid] + s_sq [64+tid] + s_sq [128+tid] + s_sq [192+tid];
            g_psum[blockIdx.x][0][c0 + tid] = s;
            g_psum[blockIdx.x][1][c0 + tid] = q;
        }
    }
}

// ===========================================================================
// stats reduce: 512 CTA partials -> 32 -> scale/shift
// ===========================================================================
__global__ void stats_mid_k()
{
    const int r = blockIdx.x;
    const int t = threadIdx.x;
    float s = 0.f, q = 0.f;
    #pragma unroll
    for (int i = 0; i < 16; ++i) {
        s += g_psum[r*16 + i][0][t];
        q += g_psum[r*16 + i][1][t];
    }
    g_pmid[r][0][t] = s;
    g_pmid[r][1][t] = q;
}

__global__ void stats_final_k(const float* __restrict__ gamma, const float* __restrict__ beta)
{
    const int t = threadIdx.x;
    float s = 0.f, q = 0.f;
    #pragma unroll
    for (int c = 0; c < 32; ++c) { s += g_pmid[c][0][t]; q += g_pmid[c][1][t]; }
    const float inv = 1.f / (float)NROWS;
    const float mean = s * inv;
    const float var  = q * inv - mean * mean;
    const float sc   = rsqrtf(var + EPS) * gamma[t];
    g_scale[t] = sc;
    g_shift[t] = beta[t] - mean * sc;
}

// ===========================================================================
// Online softmax over S fused with V-weighted sum, float4-vectorized.
// grid (BB, 16): each block covers 128 s-rows; 256 thr = 64 quad-lanes x 4 subgroups.
// ===========================================================================
__global__ void softmax_part_k(const float* __restrict__ W2, const float* __restrict__ V)
{
    __shared__ float4 smm[4][64], sml[4][64], sma[4][64];
    const int b  = blockIdx.x;
    const int sc = blockIdx.y;
    const int ql = threadIdx.x & 63;
    const int sg = threadIdx.x >> 6;
    const size_t stride = (size_t)BB * DD;
    size_t off = (size_t)(sc*128 + sg) * stride + (size_t)b * DD + ql*4;

    float4 m = make_float4(-INFINITY,-INFINITY,-INFINITY,-INFINITY);
    float4 l = make_float4(0.f,0.f,0.f,0.f);
    float4 a = make_float4(0.f,0.f,0.f,0.f);
    #pragma unroll 4
    for (int i = 0; i < 32; ++i) {
        const float4 w  = *(const float4*)(W2 + off);
        const float4 vv = *(const float4*)(V  + off);
        float4 nm;
        nm.x = fmaxf(m.x, w.x); nm.y = fmaxf(m.y, w.y);
        nm.z = fmaxf(m.z, w.z); nm.w = fmaxf(m.w, w.w);
        const float e1x = expf(m.x - nm.x), e2x = expf(w.x - nm.x);
        const float e1y = expf(m.y - nm.y), e2y = expf(w.y - nm.y);
        const float e1z = expf(m.z - nm.z), e2z = expf(w.z - nm.z);
        const float e1w = expf(m.w - nm.w), e2w = expf(w.w - nm.w);
        l.x = l.x*e1x + e2x;  a.x = a.x*e1x + e2x*vv.x;
        l.y = l.y*e1y + e2y;  a.y = a.y*e1y + e2y*vv.y;
        l.z = l.z*e1z + e2z;  a.z = a.z*e1z + e2z*vv.z;
        l.w = l.w*e1w + e2w;  a.w = a.w*e1w + e2w*vv.w;
        m = nm;
        off += 4 * stride;
    }
    smm[sg][ql] = m; sml[sg][ql] = l; sma[sg][ql] = a;
    __syncthreads();
    if (sg == 0) {
        float4 M = smm[0][ql], L = sml[0][ql], A = sma[0][ql];
        #pragma unroll
        for (int g = 1; g < 4; ++g) {
            const float4 m2 = smm[g][ql], l2 = sml[g][ql], a2 = sma[g][ql];
            float4 NM;
            NM.x = fmaxf(M.x, m2.x); NM.y = fmaxf(M.y, m2.y);
            NM.z = fmaxf(M.z, m2.z); NM.w = fmaxf(M.w, m2.w);
            const float p1x = expf(M.x-NM.x), p2x = expf(m2.x-NM.x);
            const float p1y = expf(M.y-NM.y), p2y = expf(m2.y-NM.y);
            const float p1z = expf(M.z-NM.z), p2z = expf(m2.z-NM.z);
            const float p1w = expf(M.w-NM.w), p2w = expf(m2.w-NM.w);
            L.x = L.x*p1x + l2.x*p2x;  A.x = A.x*p1x + a2.x*p2x;
            L.y = L.y*p1y + l2.y*p2y;  A.y = A.y*p1y + a2.y*p2y;
            L.z = L.z*p1z + l2.z*p2z;  A.z = A.z*p1z + a2.z*p2z;
            L.w = L.w*p1w + l2.w*p2w;  A.w = A.w*p1w + a2.w*p2w;
            M = NM;
        }
        *(float4*)&g_sm_m[sc][b][ql*4] = M;
        *(float4*)&g_sm_l[sc][b][ql*4] = L;
        *(float4*)&g_sm_a[sc][b][ql*4] = A;
    }
}

__global__ void softmax_final_k(int head)
{
    const int b = blockIdx.x;
    const int d = threadIdx.x;
    float M = -INFINITY;
    #pragma unroll
    for (int c = 0; c < 16; ++c) M = fmaxf(M, g_sm_m[c][b][d]);
    float L = 0.f, A = 0.f;
    #pragma unroll
    for (int c = 0; c < 16; ++c) {
        const float e = expf(g_sm_m[c][b][d] - M);
        L += g_sm_l[c][b][d] * e;
        A += g_sm_a[c][b][d] * e;
    }
    g_headout[b][head * DD + d] = A / L;
}

// ===========================================================================
// Final tiny MLP
// ===========================================================================
template<bool RELU, int E>
__global__ void mlp_k(const float* __restrict__ X, const float* __restrict__ W,
                      const float* __restrict__ bias, float* __restrict__ out)
{
    __shared__ float sw[E];
    __shared__ float red[4];
    const int j = blockIdx.x;
    const int t = threadIdx.x;
    for (int e = t; e < E; e += 128) sw[e] = W[(size_t)j * E + e];
    __syncthreads();
    for (int b = 0; b < BB; ++b) {
        float p = 0.f;
        for (int e = t; e < E; e += 128) p += X[(size_t)b * E + e] * sw[e];
        #pragma unroll
        for (int o = 16; o; o >>= 1) p += __shfl_xor_sync(0xffffffffu, p, o);
        if ((t & 31) == 0) red[t >> 5] = p;
        __syncthreads();
        if (t == 0) {
            float r = red[0] + red[1] + red[2] + red[3] + bias[j];
            if (RELU) r = fmaxf(r, 0.f);
            out[(size_t)b * DD + j] = r;
        }
        __syncthreads();
    }
}

// ===========================================================================
extern "C" void kernel_launch(void* const* d_in, const int* in_sizes, int n_in,
                              void* d_out, int out_size)
{
    (void)in_sizes; (void)n_in; (void)out_size;
    const float* q   = (const float*)d_in[0];
    const float* k   = (const float*)d_in[1];
    const float* v   = (const float*)d_in[2];
    const float* wq  = (const float*)d_in[3];
    const float* bq  = (const float*)d_in[4];
    const float* wk  = (const float*)d_in[5];
    const float* bk  = (const float*)d_in[6];
    const float* wv  = (const float*)d_in[7];
    const float* bv  = (const float*)d_in[8];
    const float* g1  = (const float*)d_in[9];
    const float* be1 = (const float*)d_in[10];
    const float* wl1 = (const float*)d_in[11];
    const float* bl1 = (const float*)d_in[12];
    const float* g2  = (const float*)d_in[13];
    const float* be2 = (const float*)d_in[14];
    const float* wl2 = (const float*)d_in[15];
    const float* bl2 = (const float*)d_in[16];
    const float* mw0 = (const float*)d_in[17];
    const float* mb0 = (const float*)d_in[18];
    const float* mw1 = (const float*)d_in[19];
    const float* mb1 = (const float*)d_in[20];
    const float* mw2 = (const float*)d_in[21];
    const float* mb2 = (const float*)d_in[22];
    float* out = (float*)d_out;

    float *buf = nullptr, *headout = nullptr, *m0 = nullptr, *m1 = nullptr;
    __nv_bfloat16 *whi = nullptr, *wlo = nullptr;
    cudaGetSymbolAddress((void**)&buf,     g_buf);
    cudaGetSymbolAddress((void**)&headout, g_headout);
    cudaGetSymbolAddress((void**)&m0,      g_mlp0);
    cudaGetSymbolAddress((void**)&m1,      g_mlp1);
    cudaGetSymbolAddress((void**)&whi,     g_whi);
    cudaGetSymbolAddress((void**)&wlo,     g_wlo);

    static bool attr_done = false;
    if (!attr_done) {
        cudaFuncSetAttribute(gemm_mma<0,0>, cudaFuncAttributeMaxDynamicSharedMemorySize, GSMEM);
        cudaFuncSetAttribute(gemm_mma<0,2>, cudaFuncAttributeMaxDynamicSharedMemorySize, GSMEM);
        cudaFuncSetAttribute(gemm_mma<1,1>, cudaFuncAttributeMaxDynamicSharedMemorySize, GSMEM);
        cudaFuncSetAttribute(gemm_mma<2,0>, cudaFuncAttributeMaxDynamicSharedMemorySize, GSMEM);
        attr_done = true;
    }

    const size_t SZ = (size_t)NROWS * DD;
    dim3 ggrid(NROWS / BM, DD / BNT);     // (512, 4)

    wconv_k<<<(5 * HH * DD * DD) / 256, 256>>>(wq, wk, wv, wl1, wl2);

    const float* Qc = q; const float* Kc = k; const float* Vc = v;
    for (int h = 0; h < HH; ++h) {
        float* Qn = buf + (size_t)(0 + (h & 1)) * SZ;
        float* Kn = buf + (size_t)(2 + (h & 1)) * SZ;
        float* Vn = buf + (size_t)(4 + (h & 1)) * SZ;
        float* T1 = buf + 6 * SZ;
        float* T2 = buf + 7 * SZ;
        const size_t wsz = (size_t)DD * DD;
        const __nv_bfloat16* Wq_h = whi + (h*5 + 0) * wsz; const __nv_bfloat16* Wq_l = wlo + (h*5 + 0) * wsz;
        const __nv_bfloat16* Wk_h = whi + (h*5 + 1) * wsz; const __nv_bfloat16* Wk_l = wlo + (h*5 + 1) * wsz;
        const __nv_bfloat16* Wv_h = whi + (h*5 + 2) * wsz; const __nv_bfloat16* Wv_l = wlo + (h*5 + 2) * wsz;
        const __nv_bfloat16* W1_h = whi + (h*5 + 3) * wsz; const __nv_bfloat16* W1_l = wlo + (h*5 + 3) * wsz;
        const __nv_bfloat16* W2_h = whi + (h*5 + 4) * wsz; const __nv_bfloat16* W2_l = wlo + (h*5 + 4) * wsz;

        // projections; K-GEMM fuses BN1 diff-stats vs Qn
        gemm_mma<0,0><<<ggrid, 256, GSMEM>>>(Qc, nullptr, nullptr, Wq_h, Wq_l, bq + h*DD, Qn);
        gemm_mma<0,2><<<ggrid, 256, GSMEM>>>(Kc, nullptr, Qn,      Wk_h, Wk_l, bk + h*DD, Kn);
        gemm_mma<0,0><<<ggrid, 256, GSMEM>>>(Vc, nullptr, nullptr, Wv_h, Wv_l, bv + h*DD, Vn);
        stats_mid_k<<<32, 256>>>();
        stats_final_k<<<1, 256>>>(g1 + h*DD, be1 + h*DD);

        // relu(bn1(K-Q)) @ wl1^T + bl1, fused self-stats for BN2
        gemm_mma<1,1><<<ggrid, 256, GSMEM>>>(Kn, Qn, nullptr, W1_h, W1_l, bl1 + h*DD, T1);
        stats_mid_k<<<32, 256>>>();
        stats_final_k<<<1, 256>>>(g2 + h*DD, be2 + h*DD);

        // relu(bn2(T1)) @ wl2^T + bl2
        gemm_mma<2,0><<<ggrid, 256, GSMEM>>>(T1, nullptr, nullptr, W2_h, W2_l, bl2 + h*DD, T2);

        softmax_part_k<<<dim3(BB, 16), 256>>>(T2, Vn);
        softmax_final_k<<<BB, DD>>>(h);

        Qc = Qn; Kc = Kn; Vc = Vn;
    }

    mlp_k<true,  HH*DD><<<DD, 128>>>(headout, mw0, mb0, m0);
    mlp_k<true,  DD   ><<<DD, 128>>>(m0,      mw1, mb1, m1);
    mlp_k<false, DD   ><<<DD, 128>>>(m1,      mw2, mb2, out);
}